// round 7
// baseline (speedup 1.0000x reference)
#include <cuda_runtime.h>

typedef unsigned long long ull;

#define TINYF 1e-6f
#define PIF   3.14159265358979323846f
#define NPER  4

// Per-lobe constants (L=128, H=16). Pairs (2k,2k+1), SoA [kpair][l].
// na/nb/nc are pre-scaled by |u_k|, u = W2/4.
__device__ ull   g_na2[8 * 128];
__device__ ull   g_nb2[8 * 128];
__device__ ull   g_nc2[8 * 128];
__device__ float g_A[3 * 128];     // U*sinphi
__device__ float g_B[3 * 128];     // V*sinphi
__device__ float g_C[3 * 128];     // l*cosphi
__device__ float g_w[128];         // exp(sharp*(cosphi-1))
__device__ float g_Ap[128];        // sum_k u_k * na_kl (signed u, unscaled na)
__device__ float g_Bp[128];
__device__ float g_Cp[128];
__device__ ull   g_sg2[8];         // (sgn(u_2k), sgn(u_2k+1)) as +-1.0f
__device__ ull   g_au2[8];         // (|u_2k|, |u_2k+1|)
__device__ float g_u[16];          // signed u_k

__device__ __forceinline__ ull pack2(float x, float y) {
    ull r; asm("mov.b64 %0, {%1, %2};" : "=l"(r) : "f"(x), "f"(y)); return r;
}
__device__ __forceinline__ void unpack2(ull v, float& x, float& y) {
    asm("mov.b64 {%0, %1}, %2;" : "=f"(x), "=f"(y) : "l"(v));
}
__device__ __forceinline__ ull fma2(ull a, ull b, ull c) {
    ull d; asm("fma.rn.f32x2 %0, %1, %2, %3;" : "=l"(d) : "l"(a), "l"(b), "l"(c)); return d;
}
__device__ __forceinline__ ull add2(ull a, ull b) {
    ull d; asm("add.rn.f32x2 %0, %1, %2;" : "=l"(d) : "l"(a), "l"(b)); return d;
}
__device__ __forceinline__ ull mul2(ull a, ull b) {
    ull d; asm("mul.rn.f32x2 %0, %1, %2;" : "=l"(d) : "l"(a), "l"(b)); return d;
}
__device__ __forceinline__ float tanh_fast(float x) {
    float y; asm("tanh.approx.f32 %0, %1;" : "=f"(y) : "f"(x)); return y;
}

__global__ void precompute_kernel(const float* __restrict__ lobes,
                                  const float* __restrict__ lambdas,
                                  const float* __restrict__ rot,
                                  const float* __restrict__ W1,
                                  const float* __restrict__ W2) {
    __shared__ float sM[3][16];   // M = root_rot @ W1[3:6]
    __shared__ float su[16];      // u = W2/4 (signed)
    __shared__ float sau[16];     // |u|
    int t = threadIdx.x;
    if (t < 48) {
        int d = t >> 4, k = t & 15;
        sM[d][k] = rot[d * 3 + 0] * W1[3 * 16 + k]
                 + rot[d * 3 + 1] * W1[4 * 16 + k]
                 + rot[d * 3 + 2] * W1[5 * 16 + k];
    }
    if (t < 16) {
        float u = 0.25f * W2[t];
        su[t] = u; sau[t] = fabsf(u);
    }
    __syncthreads();

    int l = t;  // blockDim.x == 128
    float lx = lobes[l * 3 + 0], ly = lobes[l * 3 + 1], lz = lobes[l * 3 + 2];
    float inv = 1.f / (sqrtf(lx * lx + ly * ly + lz * lz) + TINYF);
    lx *= inv; ly *= inv; lz *= inv;

    float ux = -ly, uy = lx, uz = 0.f;
    float invu = 1.f / (sqrtf(ux * ux + uy * uy) + TINYF);
    ux *= invu; uy *= invu;

    float vx = ly * uz - lz * uy;
    float vy = lz * ux - lx * uz;
    float vz = lx * uy - ly * ux;
    float invv = 1.f / (sqrtf(vx * vx + vy * vy + vz * vz) + TINYF);
    vx *= invv; vy *= invv; vz *= invv;

    float sharp = lambdas[l];
    float rphi  = fminf(acosf(1.f - 1.f / sharp), PIF / 3.f);
    float sp = sinf(rphi), cp = cosf(rphi);

    float Ax = ux * sp, Ay = uy * sp, Az = uz * sp;
    float Bx = vx * sp, By = vy * sp, Bz = vz * sp;
    float Cx = lx * cp, Cy = ly * cp, Cz = lz * cp;

    g_A[l] = Ax; g_A[128 + l] = Ay; g_A[256 + l] = Az;
    g_B[l] = Bx; g_B[128 + l] = By; g_B[256 + l] = Bz;
    g_C[l] = Cx; g_C[128 + l] = Cy; g_C[256 + l] = Cz;
    g_w[l] = expf(sharp * (cp - 1.f));

    float na[16], nb[16], nc[16];
#pragma unroll
    for (int k = 0; k < 16; k++) {
        na[k] = -(Ax * sM[0][k] + Ay * sM[1][k] + Az * sM[2][k]);
        nb[k] = -(Bx * sM[0][k] + By * sM[1][k] + Bz * sM[2][k]);
        nc[k] = -(Cx * sM[0][k] + Cy * sM[1][k] + Cz * sM[2][k]);
    }

    float Ap = 0.f, Bp = 0.f, Cp = 0.f;
#pragma unroll
    for (int k = 0; k < 16; k++) {
        Ap = fmaf(su[k], na[k], Ap);
        Bp = fmaf(su[k], nb[k], Bp);
        Cp = fmaf(su[k], nc[k], Cp);
    }
    g_Ap[l] = Ap; g_Bp[l] = Bp; g_Cp[l] = Cp;

#pragma unroll
    for (int kp = 0; kp < 8; kp++) {
        int k0 = 2 * kp, k1 = 2 * kp + 1;
        g_na2[kp * 128 + l] = pack2(sau[k0] * na[k0], sau[k1] * na[k1]);
        g_nb2[kp * 128 + l] = pack2(sau[k0] * nb[k0], sau[k1] * nb[k1]);
        g_nc2[kp * 128 + l] = pack2(sau[k0] * nc[k0], sau[k1] * nc[k1]);
    }
    if (l < 8) {
        g_sg2[l] = pack2(su[2 * l] >= 0.f ? 1.f : -1.f,
                         su[2 * l + 1] >= 0.f ? 1.f : -1.f);
        g_au2[l] = pack2(sau[2 * l], sau[2 * l + 1]);
    }
    if (l < 16) g_u[l] = su[l];
}

// One block handles NPER points (128 threads = 128 lobes each).
__global__ __launch_bounds__(128, 5) void vis_kernel(
    const float* __restrict__ points,
    const float* __restrict__ normals,
    const float* __restrict__ r,       // (N, 128, 8)
    const float* __restrict__ W1,      // (6, 16)
    const float* __restrict__ b1,      // (16,)
    const float* __restrict__ W2,      // (16, 1)  (folded)
    const float* __restrict__ b2,      // (1,)
    float* __restrict__ out)           // (N, 128)
{
    const int n0 = blockIdx.x * NPER;
    const int l  = threadIdx.x;

    __shared__ float s_base[NPER][16];   // points[n] @ W1[:3] + b1
    __shared__ ull   s_b2q[NPER][8];     // |u|-scaled packed base pairs
    __shared__ float s_nrm[NPER][3];
    __shared__ float s_lin0[NPER];       // b2/2 + sum_k u_k*base_k

    if (l < 16 * NPER) {
        int i = l >> 4, k = l & 15;
        int n = n0 + i;
        float px = points[n * 3 + 0], py = points[n * 3 + 1], pz = points[n * 3 + 2];
        s_base[i][k] = fmaf(px, W1[0 * 16 + k],
                       fmaf(py, W1[1 * 16 + k],
                       fmaf(pz, W1[2 * 16 + k], b1[k])));
    }
    if (l >= 64 && l < 64 + 3 * NPER) {
        int j = l - 64;
        s_nrm[j / 3][j % 3] = normals[(n0 + j / 3) * 3 + (j % 3)];
    }
    __syncthreads();

    if (l < NPER) {
        float c1 = 0.5f * b2[0];
#pragma unroll
        for (int k = 0; k < 16; k++) c1 = fmaf(g_u[k], s_base[l][k], c1);
        s_lin0[l] = c1;
    }
    if (l < 8 * NPER) {
        int i = l >> 3, kp = l & 7;
        s_b2q[i][kp] = mul2(pack2(s_base[i][2 * kp], s_base[i][2 * kp + 1]),
                            g_au2[kp]);
    }
    __syncthreads();

    // ---- Per-lobe persistent state (reused across all NPER points) ----
    ull na2[8], nb2[8], sg2[8];
#pragma unroll
    for (int kp = 0; kp < 8; kp++) {
        na2[kp] = g_na2[kp * 128 + l];
        nb2[kp] = g_nb2[kp * 128 + l];
        sg2[kp] = g_sg2[kp];            // uniform -> URs
    }

    const float wl = g_w[l];
    const ull   APB2 = pack2(g_Ap[l], g_Bp[l]);
    const float Cp = g_Cp[l];
    const float A0 = g_A[l], A1 = g_A[128 + l], A2 = g_A[256 + l];
    const float B0 = g_B[l], B1 = g_B[128 + l], B2 = g_B[256 + l];
    const float C0 = g_C[l], C1 = g_C[128 + l], C2 = g_C[256 + l];

    const float owl = __fdividef(wl, 8.f * wl + TINYF);

#pragma unroll 1
    for (int i = 0; i < NPER; i++) {
        const int n = n0 + i;
        const ull LIN2 = pack2(s_lin0[i] + Cp, 0.f);

        // Normal-gate coefficients for this point
        const float nx = s_nrm[i][0], ny = s_nrm[i][1], nz = s_nrm[i][2];
        const float ani = fmaf(A0, nx, fmaf(A1, ny, A2 * nz));
        const float bni = fmaf(B0, nx, fmaf(B1, ny, B2 * nz));
        const float cni = fmaf(C0, nx, fmaf(C1, ny, C2 * nz));

        // b22 for this point: |u|-scaled shared base pairs + scaled nc2 table (L1-hot)
        ull b22[8];
#pragma unroll
        for (int kp = 0; kp < 8; kp++)
            b22[kp] = add2(s_b2q[i][kp], g_nc2[kp * 128 + l]);

        const float* rbase = r + (size_t)(n * 128 + l) * 8;

        float vsum = 0.f;
#pragma unroll
        for (int chunk = 0; chunk < 2; chunk++) {
            const float4 rv = *reinterpret_cast<const float4*>(rbase + chunk * 4);
            float rr[4] = {rv.x, rv.y, rv.z, rv.w};
#pragma unroll
            for (int j = 0; j < 4; j++) {
                const int s = chunk * 4 + j;
                float theta = (rr[j] + (float)s) * (PIF * 0.25f);
                float st, ct;
                __sincosf(theta, &st, &ct);

                float cosn = fmaf(ct, ani, fmaf(st, bni, cni));

                ull ct2 = pack2(ct, ct);
                ull st2 = pack2(st, st);

                // acc2a carries the linear half-logit part; acc2b starts at 0.
                ull acc2a = fma2(pack2(ct, st), APB2, LIN2);
                ull acc2b = 0ULL;
#pragma unroll
                for (int kp = 0; kp < 8; kp += 2) {
                    ull h2a = fma2(ct2, na2[kp],     fma2(st2, nb2[kp],     b22[kp]));
                    ull h2b = fma2(ct2, na2[kp + 1], fma2(st2, nb2[kp + 1], b22[kp + 1]));
                    acc2a = fma2(h2a & 0x7fffffff7fffffffULL, sg2[kp],     acc2a);
                    acc2b = fma2(h2b & 0x7fffffff7fffffffULL, sg2[kp + 1], acc2b);
                }
                float a0, a1;
                unpack2(add2(acc2a, acc2b), a0, a1);

                float logit = a0 + a1;   // half-logit
                float vis = fmaf(tanh_fast(logit), 0.5f, 0.5f);
                vsum += (cosn > TINYF) ? vis : 0.f;
            }
        }

        out[n * 128 + l] = owl * vsum;
    }
}

extern "C" void kernel_launch(void* const* d_in, const int* in_sizes, int n_in,
                              void* d_out, int out_size) {
    const float* points  = (const float*)d_in[0];
    const float* normals = (const float*)d_in[1];
    const float* rot     = (const float*)d_in[2];
    const float* lobes   = (const float*)d_in[3];
    const float* lambdas = (const float*)d_in[4];
    const float* r       = (const float*)d_in[5];
    const float* W1      = (const float*)d_in[6];
    const float* b1      = (const float*)d_in[7];
    const float* W2      = (const float*)d_in[8];
    const float* b2      = (const float*)d_in[9];

    const int N = in_sizes[0] / 3;   // 8192

    precompute_kernel<<<1, 128>>>(lobes, lambdas, rot, W1, W2);
    vis_kernel<<<N / NPER, 128>>>(points, normals, r, W1, b1, W2, b2, (float*)d_out);
}

// round 8
// speedup vs baseline: 1.0615x; 1.0615x over previous
#include <cuda_runtime.h>

typedef unsigned long long ull;

#define TINYF 1e-6f
#define PIF   3.14159265358979323846f
#define NPER  4

// Per-lobe constants (L=128, H=16). Pairs (2k,2k+1), SoA [kpair][l]. na = -a, etc.
__device__ ull   g_na2[8 * 128];
__device__ ull   g_nb2[8 * 128];
__device__ ull   g_nc2[8 * 128];
__device__ float g_A[3 * 128];     // U*sinphi
__device__ float g_B[3 * 128];     // V*sinphi
__device__ float g_C[3 * 128];     // l*cosphi
__device__ float g_w[128];         // exp(sharp*(cosphi-1))
__device__ float g_Ap[128];        // sum_k u_k * na_kl   (u = W2/4, signed)
__device__ float g_Bp[128];        // sum_k u_k * nb_kl
__device__ float g_Cp[128];        // sum_k u_k * nc_kl
__device__ float g_u[16];          // u_k = W2_k / 4

__device__ __forceinline__ ull pack2(float x, float y) {
    ull r; asm("mov.b64 %0, {%1, %2};" : "=l"(r) : "f"(x), "f"(y)); return r;
}
__device__ __forceinline__ void unpack2(ull v, float& x, float& y) {
    asm("mov.b64 {%0, %1}, %2;" : "=f"(x), "=f"(y) : "l"(v));
}
__device__ __forceinline__ ull fma2(ull a, ull b, ull c) {
    ull d; asm("fma.rn.f32x2 %0, %1, %2, %3;" : "=l"(d) : "l"(a), "l"(b), "l"(c)); return d;
}
__device__ __forceinline__ ull add2(ull a, ull b) {
    ull d; asm("add.rn.f32x2 %0, %1, %2;" : "=l"(d) : "l"(a), "l"(b)); return d;
}
__device__ __forceinline__ float tanh_fast(float x) {
    float y; asm("tanh.approx.f32 %0, %1;" : "=f"(y) : "f"(x)); return y;
}

__global__ void precompute_kernel(const float* __restrict__ lobes,
                                  const float* __restrict__ lambdas,
                                  const float* __restrict__ rot,
                                  const float* __restrict__ W1,
                                  const float* __restrict__ W2) {
    __shared__ float sM[3][16];   // M = root_rot @ W1[3:6]
    __shared__ float su[16];      // u = W2/4 (signed)
    int t = threadIdx.x;
    if (t < 48) {
        int d = t >> 4, k = t & 15;
        sM[d][k] = rot[d * 3 + 0] * W1[3 * 16 + k]
                 + rot[d * 3 + 1] * W1[4 * 16 + k]
                 + rot[d * 3 + 2] * W1[5 * 16 + k];
    }
    if (t < 16) su[t] = 0.25f * W2[t];
    __syncthreads();

    int l = t;  // blockDim.x == 128
    float lx = lobes[l * 3 + 0], ly = lobes[l * 3 + 1], lz = lobes[l * 3 + 2];
    float inv = 1.f / (sqrtf(lx * lx + ly * ly + lz * lz) + TINYF);
    lx *= inv; ly *= inv; lz *= inv;

    float ux = -ly, uy = lx, uz = 0.f;
    float invu = 1.f / (sqrtf(ux * ux + uy * uy) + TINYF);
    ux *= invu; uy *= invu;

    float vx = ly * uz - lz * uy;
    float vy = lz * ux - lx * uz;
    float vz = lx * uy - ly * ux;
    float invv = 1.f / (sqrtf(vx * vx + vy * vy + vz * vz) + TINYF);
    vx *= invv; vy *= invv; vz *= invv;

    float sharp = lambdas[l];
    float rphi  = fminf(acosf(1.f - 1.f / sharp), PIF / 3.f);
    float sp = sinf(rphi), cp = cosf(rphi);

    float Ax = ux * sp, Ay = uy * sp, Az = uz * sp;
    float Bx = vx * sp, By = vy * sp, Bz = vz * sp;
    float Cx = lx * cp, Cy = ly * cp, Cz = lz * cp;

    g_A[l] = Ax; g_A[128 + l] = Ay; g_A[256 + l] = Az;
    g_B[l] = Bx; g_B[128 + l] = By; g_B[256 + l] = Bz;
    g_C[l] = Cx; g_C[128 + l] = Cy; g_C[256 + l] = Cz;
    g_w[l] = expf(sharp * (cp - 1.f));

    float na[16], nb[16], nc[16];
#pragma unroll
    for (int k = 0; k < 16; k++) {
        na[k] = -(Ax * sM[0][k] + Ay * sM[1][k] + Az * sM[2][k]);
        nb[k] = -(Bx * sM[0][k] + By * sM[1][k] + Bz * sM[2][k]);
        nc[k] = -(Cx * sM[0][k] + Cy * sM[1][k] + Cz * sM[2][k]);
    }

    float Ap = 0.f, Bp = 0.f, Cp = 0.f;
#pragma unroll
    for (int k = 0; k < 16; k++) {
        Ap = fmaf(su[k], na[k], Ap);
        Bp = fmaf(su[k], nb[k], Bp);
        Cp = fmaf(su[k], nc[k], Cp);
    }
    g_Ap[l] = Ap; g_Bp[l] = Bp; g_Cp[l] = Cp;

#pragma unroll
    for (int kp = 0; kp < 8; kp++) {
        g_na2[kp * 128 + l] = pack2(na[2 * kp], na[2 * kp + 1]);
        g_nb2[kp * 128 + l] = pack2(nb[2 * kp], nb[2 * kp + 1]);
        g_nc2[kp * 128 + l] = pack2(nc[2 * kp], nc[2 * kp + 1]);
    }
    if (l < 16) g_u[l] = su[l];
}

// One block handles NPER points (128 threads = 128 lobes each).
__global__ __launch_bounds__(128, 6) void vis_kernel(
    const float* __restrict__ points,
    const float* __restrict__ normals,
    const float* __restrict__ r,       // (N, 128, 8)
    const float* __restrict__ W1,      // (6, 16)
    const float* __restrict__ b1,      // (16,)
    const float* __restrict__ W2,      // (16, 1)  (folded)
    const float* __restrict__ b2,      // (1,)
    float* __restrict__ out)           // (N, 128)
{
    const int n0 = blockIdx.x * NPER;
    const int l  = threadIdx.x;

    __shared__ float s_base[NPER][16];   // points[n] @ W1[:3] + b1
    __shared__ ull   s_basep[NPER][8];   // packed pairs
    __shared__ float s_nrm[NPER][3];
    __shared__ float s_lin0[NPER];       // b2/2 + sum_k u_k*base_k

    if (l < 16 * NPER) {
        int i = l >> 4, k = l & 15;
        int n = n0 + i;
        float px = points[n * 3 + 0], py = points[n * 3 + 1], pz = points[n * 3 + 2];
        s_base[i][k] = fmaf(px, W1[0 * 16 + k],
                       fmaf(py, W1[1 * 16 + k],
                       fmaf(pz, W1[2 * 16 + k], b1[k])));
    }
    if (l >= 64 && l < 64 + 3 * NPER) {
        int j = l - 64;
        s_nrm[j / 3][j % 3] = normals[(n0 + j / 3) * 3 + (j % 3)];
    }
    __syncthreads();

    if (l < NPER) {
        float c1 = 0.5f * b2[0];
#pragma unroll
        for (int k = 0; k < 16; k++) c1 = fmaf(g_u[k], s_base[l][k], c1);
        s_lin0[l] = c1;
    }
    if (l < 8 * NPER) {
        int i = l >> 3, kp = l & 7;
        s_basep[i][kp] = pack2(s_base[i][2 * kp], s_base[i][2 * kp + 1]);
    }
    __syncthreads();

    // ---- Per-lobe persistent state (reused across all NPER points) ----
    ull na2[8], nb2[8];
    float u[16];
#pragma unroll
    for (int kp = 0; kp < 8; kp++) {
        na2[kp] = g_na2[kp * 128 + l];
        nb2[kp] = g_nb2[kp * 128 + l];
    }
#pragma unroll
    for (int k = 0; k < 16; k++) u[k] = g_u[k];   // uniform -> URs

    const float wl = g_w[l];
    const float Ap = g_Ap[l], Bp = g_Bp[l], Cp = g_Cp[l];
    const float A0 = g_A[l], A1 = g_A[128 + l], A2 = g_A[256 + l];
    const float B0 = g_B[l], B1 = g_B[128 + l], B2 = g_B[256 + l];
    const float C0 = g_C[l], C1 = g_C[128 + l], C2 = g_C[256 + l];

    const float owl = __fdividef(wl, 8.f * wl + TINYF);

#pragma unroll 1
    for (int i = 0; i < NPER; i++) {
        const int n = n0 + i;
        const float lin = s_lin0[i] + Cp;

        // Normal-gate coefficients for this point (3 LDS + 9 FFMA)
        const float nx = s_nrm[i][0], ny = s_nrm[i][1], nz = s_nrm[i][2];
        const float ani = fmaf(A0, nx, fmaf(A1, ny, A2 * nz));
        const float bni = fmaf(B0, nx, fmaf(B1, ny, B2 * nz));
        const float cni = fmaf(C0, nx, fmaf(C1, ny, C2 * nz));

        // Packed dual chains: lane0 = cosn gate, lane1 = linear half-logit part.
        const ull P1 = pack2(ani, Ap);
        const ull P2 = pack2(bni, Bp);
        const ull P3 = pack2(cni, lin);

        // b22 for this point: shared base pairs + L1-hot nc2 table
        ull b22[8];
#pragma unroll
        for (int kp = 0; kp < 8; kp++)
            b22[kp] = add2(s_basep[i][kp], g_nc2[kp * 128 + l]);

        const float* rbase = r + (size_t)(n * 128 + l) * 8;

        float vsum = 0.f;
#pragma unroll
        for (int chunk = 0; chunk < 2; chunk++) {
            const float4 rv = *reinterpret_cast<const float4*>(rbase + chunk * 4);
            float rr[4] = {rv.x, rv.y, rv.z, rv.w};
#pragma unroll
            for (int j = 0; j < 4; j++) {
                const int s = chunk * 4 + j;
                float theta = (rr[j] + (float)s) * (PIF * 0.25f);
                float st, ct;
                __sincosf(theta, &st, &ct);

                ull ct2 = pack2(ct, ct);
                ull st2 = pack2(st, st);

                // (cosn, linpart) in one packed chain
                float cosn, linpart;
                unpack2(fma2(ct2, P1, fma2(st2, P2, P3)), cosn, linpart);

                float acc0 = linpart, acc1 = 0.f;
#pragma unroll
                for (int kp = 0; kp < 8; kp++) {
                    ull h2 = fma2(ct2, na2[kp], fma2(st2, nb2[kp], b22[kp]));
                    float hlo, hhi;
                    unpack2(h2, hlo, hhi);
                    acc0 = fmaf(fabsf(hlo), u[2 * kp + 0], acc0);   // |src| folds into FFMA
                    acc1 = fmaf(fabsf(hhi), u[2 * kp + 1], acc1);
                }
                // half-logit
                float logit = acc0 + acc1;
                float vis = fmaf(tanh_fast(logit), 0.5f, 0.5f);
                vsum += (cosn > TINYF) ? vis : 0.f;
            }
        }

        out[n * 128 + l] = owl * vsum;
    }
}

extern "C" void kernel_launch(void* const* d_in, const int* in_sizes, int n_in,
                              void* d_out, int out_size) {
    const float* points  = (const float*)d_in[0];
    const float* normals = (const float*)d_in[1];
    const float* rot     = (const float*)d_in[2];
    const float* lobes   = (const float*)d_in[3];
    const float* lambdas = (const float*)d_in[4];
    const float* r       = (const float*)d_in[5];
    const float* W1      = (const float*)d_in[6];
    const float* b1      = (const float*)d_in[7];
    const float* W2      = (const float*)d_in[8];
    const float* b2      = (const float*)d_in[9];

    const int N = in_sizes[0] / 3;   // 8192

    precompute_kernel<<<1, 128>>>(lobes, lambdas, rot, W1, W2);
    vis_kernel<<<N / NPER, 128>>>(points, normals, r, W1, b1, W2, b2, (float*)d_out);
}

// round 9
// speedup vs baseline: 1.0635x; 1.0020x over previous
#include <cuda_runtime.h>

typedef unsigned long long ull;

#define TINYF 1e-6f
#define PIF   3.14159265358979323846f
#define PI4F  0.78539816339744830962f
#define NPER  4

// Per-lobe constants (L=128, H=16). Pairs (2k,2k+1), SoA [kpair][l]. na = -a, etc.
__device__ ull   g_na2[8 * 128];
__device__ ull   g_nb2[8 * 128];
__device__ ull   g_nc2[8 * 128];
__device__ float g_A[3 * 128];     // U*sinphi
__device__ float g_B[3 * 128];     // V*sinphi
__device__ float g_C[3 * 128];     // l*cosphi
__device__ float g_w[128];         // exp(sharp*(cosphi-1))
__device__ float g_Ap[128];        // sum_k u_k * na_kl   (u = W2/4, signed)
__device__ float g_Bp[128];
__device__ float g_Cp[128];
__device__ float g_u[16];          // u_k = W2_k / 4

__device__ __forceinline__ ull pack2(float x, float y) {
    ull r; asm("mov.b64 %0, {%1, %2};" : "=l"(r) : "f"(x), "f"(y)); return r;
}
__device__ __forceinline__ void unpack2(ull v, float& x, float& y) {
    asm("mov.b64 {%0, %1}, %2;" : "=f"(x), "=f"(y) : "l"(v));
}
__device__ __forceinline__ ull fma2(ull a, ull b, ull c) {
    ull d; asm("fma.rn.f32x2 %0, %1, %2, %3;" : "=l"(d) : "l"(a), "l"(b), "l"(c)); return d;
}
__device__ __forceinline__ ull add2(ull a, ull b) {
    ull d; asm("add.rn.f32x2 %0, %1, %2;" : "=l"(d) : "l"(a), "l"(b)); return d;
}
__device__ __forceinline__ float tanh_fast(float x) {
    float y; asm("tanh.approx.f32 %0, %1;" : "=f"(y) : "f"(x)); return y;
}

__global__ void precompute_kernel(const float* __restrict__ lobes,
                                  const float* __restrict__ lambdas,
                                  const float* __restrict__ rot,
                                  const float* __restrict__ W1,
                                  const float* __restrict__ W2) {
    __shared__ float sM[3][16];   // M = root_rot @ W1[3:6]
    __shared__ float su[16];      // u = W2/4 (signed)
    int t = threadIdx.x;
    if (t < 48) {
        int d = t >> 4, k = t & 15;
        sM[d][k] = rot[d * 3 + 0] * W1[3 * 16 + k]
                 + rot[d * 3 + 1] * W1[4 * 16 + k]
                 + rot[d * 3 + 2] * W1[5 * 16 + k];
    }
    if (t < 16) su[t] = 0.25f * W2[t];
    __syncthreads();

    int l = t;  // blockDim.x == 128
    float lx = lobes[l * 3 + 0], ly = lobes[l * 3 + 1], lz = lobes[l * 3 + 2];
    float inv = 1.f / (sqrtf(lx * lx + ly * ly + lz * lz) + TINYF);
    lx *= inv; ly *= inv; lz *= inv;

    float ux = -ly, uy = lx, uz = 0.f;
    float invu = 1.f / (sqrtf(ux * ux + uy * uy) + TINYF);
    ux *= invu; uy *= invu;

    float vx = ly * uz - lz * uy;
    float vy = lz * ux - lx * uz;
    float vz = lx * uy - ly * ux;
    float invv = 1.f / (sqrtf(vx * vx + vy * vy + vz * vz) + TINYF);
    vx *= invv; vy *= invv; vz *= invv;

    float sharp = lambdas[l];
    float rphi  = fminf(acosf(1.f - 1.f / sharp), PIF / 3.f);
    float sp = sinf(rphi), cp = cosf(rphi);

    float Ax = ux * sp, Ay = uy * sp, Az = uz * sp;
    float Bx = vx * sp, By = vy * sp, Bz = vz * sp;
    float Cx = lx * cp, Cy = ly * cp, Cz = lz * cp;

    g_A[l] = Ax; g_A[128 + l] = Ay; g_A[256 + l] = Az;
    g_B[l] = Bx; g_B[128 + l] = By; g_B[256 + l] = Bz;
    g_C[l] = Cx; g_C[128 + l] = Cy; g_C[256 + l] = Cz;
    g_w[l] = expf(sharp * (cp - 1.f));

    float na[16], nb[16], nc[16];
#pragma unroll
    for (int k = 0; k < 16; k++) {
        na[k] = -(Ax * sM[0][k] + Ay * sM[1][k] + Az * sM[2][k]);
        nb[k] = -(Bx * sM[0][k] + By * sM[1][k] + Bz * sM[2][k]);
        nc[k] = -(Cx * sM[0][k] + Cy * sM[1][k] + Cz * sM[2][k]);
    }

    float Ap = 0.f, Bp = 0.f, Cp = 0.f;
#pragma unroll
    for (int k = 0; k < 16; k++) {
        Ap = fmaf(su[k], na[k], Ap);
        Bp = fmaf(su[k], nb[k], Bp);
        Cp = fmaf(su[k], nc[k], Cp);
    }
    g_Ap[l] = Ap; g_Bp[l] = Bp; g_Cp[l] = Cp;

#pragma unroll
    for (int kp = 0; kp < 8; kp++) {
        g_na2[kp * 128 + l] = pack2(na[2 * kp], na[2 * kp + 1]);
        g_nb2[kp * 128 + l] = pack2(nb[2 * kp], nb[2 * kp + 1]);
        g_nc2[kp * 128 + l] = pack2(nc[2 * kp], nc[2 * kp + 1]);
    }
    if (l < 16) g_u[l] = su[l];
}

// One block handles NPER points (128 threads = 128 lobes each).
__global__ __launch_bounds__(128, 5) void vis_kernel(
    const float* __restrict__ points,
    const float* __restrict__ normals,
    const float* __restrict__ r,       // (N, 128, 8)
    const float* __restrict__ W1,      // (6, 16)
    const float* __restrict__ b1,      // (16,)
    const float* __restrict__ W2,      // (16, 1)  (folded)
    const float* __restrict__ b2,      // (1,)
    float* __restrict__ out)           // (N, 128)
{
    const int n0 = blockIdx.x * NPER;
    const int l  = threadIdx.x;

    __shared__ float s_base[NPER][16];   // points[n] @ W1[:3] + b1
    __shared__ ull   s_basep[NPER][8];   // packed pairs
    __shared__ float s_nrm[NPER][3];
    __shared__ float s_lin0[NPER];       // b2/2 + sum_k u_k*base_k

    if (l < 16 * NPER) {
        int i = l >> 4, k = l & 15;
        int n = n0 + i;
        float px = points[n * 3 + 0], py = points[n * 3 + 1], pz = points[n * 3 + 2];
        s_base[i][k] = fmaf(px, W1[0 * 16 + k],
                       fmaf(py, W1[1 * 16 + k],
                       fmaf(pz, W1[2 * 16 + k], b1[k])));
    }
    if (l >= 64 && l < 64 + 3 * NPER) {
        int j = l - 64;
        s_nrm[j / 3][j % 3] = normals[(n0 + j / 3) * 3 + (j % 3)];
    }
    __syncthreads();

    if (l < NPER) {
        float c1 = 0.5f * b2[0];
#pragma unroll
        for (int k = 0; k < 16; k++) c1 = fmaf(g_u[k], s_base[l][k], c1);
        s_lin0[l] = c1;
    }
    if (l < 8 * NPER) {
        int i = l >> 3, kp = l & 7;
        s_basep[i][kp] = pack2(s_base[i][2 * kp], s_base[i][2 * kp + 1]);
    }
    __syncthreads();

    // ---- Per-lobe persistent state (reused across all NPER points) ----
    ull na2[8], nb2[8];
    float u[16];
#pragma unroll
    for (int kp = 0; kp < 8; kp++) {
        na2[kp] = g_na2[kp * 128 + l];
        nb2[kp] = g_nb2[kp * 128 + l];
    }
#pragma unroll
    for (int k = 0; k < 16; k++) u[k] = g_u[k];   // uniform -> URs

    const float wl = g_w[l];
    const float Ap = g_Ap[l], Bp = g_Bp[l], Cp = g_Cp[l];
    const float A0 = g_A[l], A1 = g_A[128 + l], A2 = g_A[256 + l];
    const float B0 = g_B[l], B1 = g_B[128 + l], B2 = g_B[256 + l];
    const float C0 = g_C[l], C1 = g_C[128 + l], C2 = g_C[256 + l];

    const float owl = __fdividef(wl, 8.f * wl + TINYF);

#pragma unroll 1
    for (int i = 0; i < NPER; i++) {
        const int n = n0 + i;
        const float lin = s_lin0[i] + Cp;

        // Normal-gate coefficients for this point (3 LDS + 9 FFMA)
        const float nx = s_nrm[i][0], ny = s_nrm[i][1], nz = s_nrm[i][2];
        const float ani = fmaf(A0, nx, fmaf(A1, ny, A2 * nz));
        const float bni = fmaf(B0, nx, fmaf(B1, ny, B2 * nz));
        const float cni = fmaf(C0, nx, fmaf(C1, ny, C2 * nz));

        // Packed dual chains: lane0 = cosn gate, lane1 = linear half-logit part.
        const ull P1 = pack2(ani, Ap);
        const ull P2 = pack2(bni, Bp);
        const ull P3 = pack2(cni, lin);

        // b22 for this point: shared base pairs + L1-hot nc2 table
        ull b22[8];
#pragma unroll
        for (int kp = 0; kp < 8; kp++)
            b22[kp] = add2(s_basep[i][kp], g_nc2[kp * 128 + l]);

        const float* rbase = r + (size_t)(n * 128 + l) * 8;

        float vsum = 0.f;
#pragma unroll
        for (int chunk = 0; chunk < 2; chunk++) {
            const float4 rv = *reinterpret_cast<const float4*>(rbase + chunk * 4);
            float rr[4] = {rv.x, rv.y, rv.z, rv.w};
#pragma unroll
            for (int j = 0; j < 4; j++) {
                const int s = chunk * 4 + j;
                // theta = rr*(pi/4) + s*(pi/4): FFMA with immediate multiplier (rt=1)
                float theta = fmaf(rr[j], PI4F, (float)s * PI4F);
                float st, ct;
                __sincosf(theta, &st, &ct);

                ull ct2 = pack2(ct, ct);
                ull st2 = pack2(st, st);

                // (cosn, linpart) in one packed chain
                float cosn, linpart;
                unpack2(fma2(ct2, P1, fma2(st2, P2, P3)), cosn, linpart);

                float acc0 = linpart, acc1 = 0.f;
#pragma unroll
                for (int kp = 0; kp < 8; kp++) {
                    ull h2 = fma2(ct2, na2[kp], fma2(st2, nb2[kp], b22[kp]));
                    float hlo, hhi;
                    unpack2(h2, hlo, hhi);
                    acc0 = fmaf(fabsf(hlo), u[2 * kp + 0], acc0);   // |src| folds into FFMA
                    acc1 = fmaf(fabsf(hhi), u[2 * kp + 1], acc1);
                }
                // vis = sel + sel*tanh(half_logit), sel = gate ? 0.5 : 0
                float sel = (cosn > TINYF) ? 0.5f : 0.f;
                float t  = tanh_fast(acc0 + acc1);
                vsum = fmaf(t, sel, vsum + sel);
            }
        }

        out[n * 128 + l] = owl * vsum;
    }
}

extern "C" void kernel_launch(void* const* d_in, const int* in_sizes, int n_in,
                              void* d_out, int out_size) {
    const float* points  = (const float*)d_in[0];
    const float* normals = (const float*)d_in[1];
    const float* rot     = (const float*)d_in[2];
    const float* lobes   = (const float*)d_in[3];
    const float* lambdas = (const float*)d_in[4];
    const float* r       = (const float*)d_in[5];
    const float* W1      = (const float*)d_in[6];
    const float* b1      = (const float*)d_in[7];
    const float* W2      = (const float*)d_in[8];
    const float* b2      = (const float*)d_in[9];

    const int N = in_sizes[0] / 3;   // 8192

    precompute_kernel<<<1, 128>>>(lobes, lambdas, rot, W1, W2);
    vis_kernel<<<N / NPER, 128>>>(points, normals, r, W1, b1, W2, b2, (float*)d_out);
}

// round 10
// speedup vs baseline: 1.0957x; 1.0302x over previous
#include <cuda_runtime.h>

typedef unsigned long long ull;

#define TINYF 1e-6f
#define PIF   3.14159265358979323846f
#define PI4F  0.78539816339744830962f
#define NPER  4

// Per-lobe constants (L=128, H=16). Pairs (2k,2k+1), SoA [kpair][l]. na = -a, etc.
__device__ ull   g_na2[8 * 128];
__device__ ull   g_nb2[8 * 128];
__device__ ull   g_nc2[8 * 128];
__device__ float g_A[3 * 128];     // U*sinphi
__device__ float g_B[3 * 128];     // V*sinphi
__device__ float g_C[3 * 128];     // l*cosphi
__device__ float g_w[128];         // exp(sharp*(cosphi-1))
__device__ float g_Ap[128];        // sum_k u_k * na_kl   (u = W2/4, signed)
__device__ float g_Bp[128];
__device__ float g_Cp[128];
__device__ float g_u[16];          // u_k = W2_k / 4

__device__ __forceinline__ ull pack2(float x, float y) {
    ull r; asm("mov.b64 %0, {%1, %2};" : "=l"(r) : "f"(x), "f"(y)); return r;
}
__device__ __forceinline__ void unpack2(ull v, float& x, float& y) {
    asm("mov.b64 {%0, %1}, %2;" : "=f"(x), "=f"(y) : "l"(v));
}
__device__ __forceinline__ ull fma2(ull a, ull b, ull c) {
    ull d; asm("fma.rn.f32x2 %0, %1, %2, %3;" : "=l"(d) : "l"(a), "l"(b), "l"(c)); return d;
}
__device__ __forceinline__ ull add2(ull a, ull b) {
    ull d; asm("add.rn.f32x2 %0, %1, %2;" : "=l"(d) : "l"(a), "l"(b)); return d;
}
__device__ __forceinline__ float tanh_fast(float x) {
    float y; asm("tanh.approx.f32 %0, %1;" : "=f"(y) : "f"(x)); return y;
}

__global__ void precompute_kernel(const float* __restrict__ lobes,
                                  const float* __restrict__ lambdas,
                                  const float* __restrict__ rot,
                                  const float* __restrict__ W1,
                                  const float* __restrict__ W2) {
    __shared__ float sM[3][16];   // M = root_rot @ W1[3:6]
    __shared__ float su[16];      // u = W2/4 (signed)
    int t = threadIdx.x;
    if (t < 48) {
        int d = t >> 4, k = t & 15;
        sM[d][k] = rot[d * 3 + 0] * W1[3 * 16 + k]
                 + rot[d * 3 + 1] * W1[4 * 16 + k]
                 + rot[d * 3 + 2] * W1[5 * 16 + k];
    }
    if (t < 16) su[t] = 0.25f * W2[t];
    __syncthreads();

    int l = t;  // blockDim.x == 128
    float lx = lobes[l * 3 + 0], ly = lobes[l * 3 + 1], lz = lobes[l * 3 + 2];
    float inv = 1.f / (sqrtf(lx * lx + ly * ly + lz * lz) + TINYF);
    lx *= inv; ly *= inv; lz *= inv;

    float ux = -ly, uy = lx, uz = 0.f;
    float invu = 1.f / (sqrtf(ux * ux + uy * uy) + TINYF);
    ux *= invu; uy *= invu;

    float vx = ly * uz - lz * uy;
    float vy = lz * ux - lx * uz;
    float vz = lx * uy - ly * ux;
    float invv = 1.f / (sqrtf(vx * vx + vy * vy + vz * vz) + TINYF);
    vx *= invv; vy *= invv; vz *= invv;

    float sharp = lambdas[l];
    float rphi  = fminf(acosf(1.f - 1.f / sharp), PIF / 3.f);
    float sp = sinf(rphi), cp = cosf(rphi);

    float Ax = ux * sp, Ay = uy * sp, Az = uz * sp;
    float Bx = vx * sp, By = vy * sp, Bz = vz * sp;
    float Cx = lx * cp, Cy = ly * cp, Cz = lz * cp;

    g_A[l] = Ax; g_A[128 + l] = Ay; g_A[256 + l] = Az;
    g_B[l] = Bx; g_B[128 + l] = By; g_B[256 + l] = Bz;
    g_C[l] = Cx; g_C[128 + l] = Cy; g_C[256 + l] = Cz;
    g_w[l] = expf(sharp * (cp - 1.f));

    float na[16], nb[16], nc[16];
#pragma unroll
    for (int k = 0; k < 16; k++) {
        na[k] = -(Ax * sM[0][k] + Ay * sM[1][k] + Az * sM[2][k]);
        nb[k] = -(Bx * sM[0][k] + By * sM[1][k] + Bz * sM[2][k]);
        nc[k] = -(Cx * sM[0][k] + Cy * sM[1][k] + Cz * sM[2][k]);
    }

    float Ap = 0.f, Bp = 0.f, Cp = 0.f;
#pragma unroll
    for (int k = 0; k < 16; k++) {
        Ap = fmaf(su[k], na[k], Ap);
        Bp = fmaf(su[k], nb[k], Bp);
        Cp = fmaf(su[k], nc[k], Cp);
    }
    g_Ap[l] = Ap; g_Bp[l] = Bp; g_Cp[l] = Cp;

#pragma unroll
    for (int kp = 0; kp < 8; kp++) {
        g_na2[kp * 128 + l] = pack2(na[2 * kp], na[2 * kp + 1]);
        g_nb2[kp * 128 + l] = pack2(nb[2 * kp], nb[2 * kp + 1]);
        g_nc2[kp * 128 + l] = pack2(nc[2 * kp], nc[2 * kp + 1]);
    }
    if (l < 16) g_u[l] = su[l];
}

// One block handles NPER points (128 threads = 128 lobes each).
__global__ __launch_bounds__(128, 5) void vis_kernel(
    const float* __restrict__ points,
    const float* __restrict__ normals,
    const float* __restrict__ r,       // (N, 128, 8)
    const float* __restrict__ W1,      // (6, 16)
    const float* __restrict__ b1,      // (16,)
    const float* __restrict__ W2,      // (16, 1)  (folded)
    const float* __restrict__ b2,      // (1,)
    float* __restrict__ out)           // (N, 128)
{
    const int n0 = blockIdx.x * NPER;
    const int l  = threadIdx.x;

    __shared__ float s_base[NPER][16];   // points[n] @ W1[:3] + b1
    __shared__ ull   s_basep[NPER][8];   // packed pairs
    __shared__ float s_nrm[NPER][3];
    __shared__ float s_lin0[NPER];       // b2/2 + sum_k u_k*base_k

    if (l < 16 * NPER) {
        int i = l >> 4, k = l & 15;
        int n = n0 + i;
        float px = points[n * 3 + 0], py = points[n * 3 + 1], pz = points[n * 3 + 2];
        s_base[i][k] = fmaf(px, W1[0 * 16 + k],
                       fmaf(py, W1[1 * 16 + k],
                       fmaf(pz, W1[2 * 16 + k], b1[k])));
    }
    if (l >= 64 && l < 64 + 3 * NPER) {
        int j = l - 64;
        s_nrm[j / 3][j % 3] = normals[(n0 + j / 3) * 3 + (j % 3)];
    }
    __syncthreads();

    if (l < NPER) {
        float c1 = 0.5f * b2[0];
#pragma unroll
        for (int k = 0; k < 16; k++) c1 = fmaf(g_u[k], s_base[l][k], c1);
        s_lin0[l] = c1;
    }
    if (l < 8 * NPER) {
        int i = l >> 3, kp = l & 7;
        s_basep[i][kp] = pack2(s_base[i][2 * kp], s_base[i][2 * kp + 1]);
    }
    __syncthreads();

    // ---- Per-lobe persistent state (reused across all NPER points) ----
    ull na2[8], nb2[8];
    float u[16];
#pragma unroll
    for (int kp = 0; kp < 8; kp++) {
        na2[kp] = g_na2[kp * 128 + l];
        nb2[kp] = g_nb2[kp * 128 + l];
    }
#pragma unroll
    for (int k = 0; k < 16; k++) u[k] = g_u[k];   // uniform -> URs

    const float wl = g_w[l];
    const float Ap = g_Ap[l], Bp = g_Bp[l], Cp = g_Cp[l];
    const float A0 = g_A[l], A1 = g_A[128 + l], A2 = g_A[256 + l];
    const float B0 = g_B[l], B1 = g_B[128 + l], B2 = g_B[256 + l];
    const float C0 = g_C[l], C1 = g_C[128 + l], C2 = g_C[256 + l];

    const float owl = __fdividef(wl, 8.f * wl + TINYF);

#pragma unroll 1
    for (int i = 0; i < NPER; i++) {
        const int n = n0 + i;
        const float lin = s_lin0[i] + Cp;

        // Normal-gate coefficients for this point (3 LDS + 9 FFMA)
        const float nx = s_nrm[i][0], ny = s_nrm[i][1], nz = s_nrm[i][2];
        const float ani = fmaf(A0, nx, fmaf(A1, ny, A2 * nz));
        const float bni = fmaf(B0, nx, fmaf(B1, ny, B2 * nz));
        const float cni = fmaf(C0, nx, fmaf(C1, ny, C2 * nz));

        // Packed dual chains: lane0 = cosn gate, lane1 = linear half-logit part.
        const ull P1 = pack2(ani, Ap);
        const ull P2 = pack2(bni, Bp);
        const ull P3 = pack2(cni, lin);

        // b22 for this point: shared base pairs + L1-hot nc2 table
        ull b22[8];
#pragma unroll
        for (int kp = 0; kp < 8; kp++)
            b22[kp] = add2(s_basep[i][kp], g_nc2[kp * 128 + l]);

        const float* rbase = r + (size_t)(n * 128 + l) * 8;

        float vs0 = 0.f, vs1 = 0.f;   // split vsum chains (one per chunk)
#pragma unroll
        for (int chunk = 0; chunk < 2; chunk++) {
            const float4 rv = *reinterpret_cast<const float4*>(rbase + chunk * 4);
            float rr[4] = {rv.x, rv.y, rv.z, rv.w};
            float vloc = 0.f;
#pragma unroll
            for (int j = 0; j < 4; j++) {
                const int s = chunk * 4 + j;
                // theta = rr*(pi/4) + s*(pi/4): FFMA with immediate multiplier
                float theta = fmaf(rr[j], PI4F, (float)s * PI4F);
                float st, ct;
                __sincosf(theta, &st, &ct);

                ull ct2 = pack2(ct, ct);
                ull st2 = pack2(st, st);

                // (cosn, linpart) in one packed chain
                float cosn, linpart;
                unpack2(fma2(ct2, P1, fma2(st2, P2, P3)), cosn, linpart);

                // 4 independent accumulator chains, depth 4 each
                float a0 = linpart, a1 = 0.f, a2 = 0.f, a3 = 0.f;
#pragma unroll
                for (int kp = 0; kp < 8; kp += 2) {
                    ull h2e = fma2(ct2, na2[kp],     fma2(st2, nb2[kp],     b22[kp]));
                    ull h2o = fma2(ct2, na2[kp + 1], fma2(st2, nb2[kp + 1], b22[kp + 1]));
                    float e0, e1, o0, o1;
                    unpack2(h2e, e0, e1);
                    unpack2(h2o, o0, o1);
                    a0 = fmaf(fabsf(e0), u[2 * kp + 0], a0);
                    a1 = fmaf(fabsf(e1), u[2 * kp + 1], a1);
                    a2 = fmaf(fabsf(o0), u[2 * kp + 2], a2);
                    a3 = fmaf(fabsf(o1), u[2 * kp + 3], a3);
                }
                float logit = (a0 + a2) + (a1 + a3);   // half-logit
                float vis = fmaf(tanh_fast(logit), 0.5f, 0.5f);
                vloc += (cosn > TINYF) ? vis : 0.f;
            }
            if (chunk == 0) vs0 = vloc; else vs1 = vloc;
        }

        out[n * 128 + l] = owl * (vs0 + vs1);
    }
}

extern "C" void kernel_launch(void* const* d_in, const int* in_sizes, int n_in,
                              void* d_out, int out_size) {
    const float* points  = (const float*)d_in[0];
    const float* normals = (const float*)d_in[1];
    const float* rot     = (const float*)d_in[2];
    const float* lobes   = (const float*)d_in[3];
    const float* lambdas = (const float*)d_in[4];
    const float* r       = (const float*)d_in[5];
    const float* W1      = (const float*)d_in[6];
    const float* b1      = (const float*)d_in[7];
    const float* W2      = (const float*)d_in[8];
    const float* b2      = (const float*)d_in[9];

    const int N = in_sizes[0] / 3;   // 8192

    precompute_kernel<<<1, 128>>>(lobes, lambdas, rot, W1, W2);
    vis_kernel<<<N / NPER, 128>>>(points, normals, r, W1, b1, W2, b2, (float*)d_out);
}